// round 1
// baseline (speedup 1.0000x reference)
#include <cuda_runtime.h>
#include <cuda_bf16.h>
#include <cstdint>

// ----------------------------------------------------------------------------
// IndRNN: out[b,t,u] = h_t where h_t = relu(x_t @ W + b + h_{t-1} * clip(u,0,1))
// Phase 1: SGEMM proj = x@W + bias  -> written directly into d_out ([B,T,U])
// Phase 2: in-place sequential scan over t per (b,u) chain.
// ----------------------------------------------------------------------------

#define BM 128
#define BN 128
#define BK 8
#define TM 8
#define TN 8
// 256 threads per block; each thread computes an 8x8 tile of C.

__global__ __launch_bounds__(256, 2)
void sgemm_bias_kernel(const float* __restrict__ A,   // [M,K] row-major (x)
                       const float* __restrict__ Bm,  // [K,N] row-major (W)
                       const float* __restrict__ bias,// [N]
                       float* __restrict__ C,         // [M,N]
                       int M, int N, int K)
{
    __shared__ float As[BK][BM];   // transposed A tile
    __shared__ float Bs[BK][BN];

    const int bx = blockIdx.x;     // N tile index
    const int by = blockIdx.y;     // M tile index
    const int tid = threadIdx.x;

    // A tile load mapping: 128 rows x 8 cols = 1024 floats = 256 float4
    const int aRow  = tid >> 1;          // 0..127
    const int aCol4 = (tid & 1) * 4;     // 0 or 4
    // B tile load mapping: 8 rows x 128 cols = 1024 floats = 256 float4
    const int bRow  = tid >> 5;          // 0..7
    const int bCol4 = (tid & 31) * 4;    // 0..124

    const int ty = tid >> 4;             // 0..15
    const int tx = tid & 15;             // 0..15

    const float* Aptr = A + (size_t)(by * BM) * K;
    const float* Bptr = Bm + bx * BN;

    float acc[TM][TN];
    #pragma unroll
    for (int i = 0; i < TM; i++)
        #pragma unroll
        for (int j = 0; j < TN; j++)
            acc[i][j] = 0.0f;

    for (int k0 = 0; k0 < K; k0 += BK) {
        // Load A tile (transposed into As)
        float4 a4 = *reinterpret_cast<const float4*>(Aptr + (size_t)aRow * K + k0 + aCol4);
        As[aCol4 + 0][aRow] = a4.x;
        As[aCol4 + 1][aRow] = a4.y;
        As[aCol4 + 2][aRow] = a4.z;
        As[aCol4 + 3][aRow] = a4.w;
        // Load B tile
        float4 b4 = *reinterpret_cast<const float4*>(Bptr + (size_t)(k0 + bRow) * N + bCol4);
        *reinterpret_cast<float4*>(&Bs[bRow][bCol4]) = b4;
        __syncthreads();

        #pragma unroll
        for (int k = 0; k < BK; k++) {
            float ar[TM], br[TN];
            float4 ar0 = *reinterpret_cast<const float4*>(&As[k][ty * TM]);
            float4 ar1 = *reinterpret_cast<const float4*>(&As[k][ty * TM + 4]);
            ar[0]=ar0.x; ar[1]=ar0.y; ar[2]=ar0.z; ar[3]=ar0.w;
            ar[4]=ar1.x; ar[5]=ar1.y; ar[6]=ar1.z; ar[7]=ar1.w;
            float4 br0 = *reinterpret_cast<const float4*>(&Bs[k][tx * TN]);
            float4 br1 = *reinterpret_cast<const float4*>(&Bs[k][tx * TN + 4]);
            br[0]=br0.x; br[1]=br0.y; br[2]=br0.z; br[3]=br0.w;
            br[4]=br1.x; br[5]=br1.y; br[6]=br1.z; br[7]=br1.w;
            #pragma unroll
            for (int i = 0; i < TM; i++)
                #pragma unroll
                for (int j = 0; j < TN; j++)
                    acc[i][j] = fmaf(ar[i], br[j], acc[i][j]);
        }
        __syncthreads();
    }

    // Epilogue: add bias, write out (vectorized)
    const int cColBase = bx * BN + tx * TN;
    float4 bias0 = *reinterpret_cast<const float4*>(bias + cColBase);
    float4 bias1 = *reinterpret_cast<const float4*>(bias + cColBase + 4);
    #pragma unroll
    for (int i = 0; i < TM; i++) {
        const size_t row = (size_t)(by * BM) + ty * TM + i;
        float4 o0, o1;
        o0.x = acc[i][0] + bias0.x; o0.y = acc[i][1] + bias0.y;
        o0.z = acc[i][2] + bias0.z; o0.w = acc[i][3] + bias0.w;
        o1.x = acc[i][4] + bias1.x; o1.y = acc[i][5] + bias1.y;
        o1.z = acc[i][6] + bias1.z; o1.w = acc[i][7] + bias1.w;
        *reinterpret_cast<float4*>(C + row * N + cColBase)     = o0;
        *reinterpret_cast<float4*>(C + row * N + cColBase + 4) = o1;
    }
}

// ----------------------------------------------------------------------------
// Phase 2: in-place recurrence over t. One thread per (b,u) chain.
// 8-way unroll over t: batch 8 loads (MLP=8), then 8 dependent fma+relu steps.
// ----------------------------------------------------------------------------
__global__ __launch_bounds__(256)
void indrnn_scan_kernel(float* __restrict__ P,        // [B,T,U] in-place
                        const float* __restrict__ h0, // [B,U]
                        const float* __restrict__ u,  // [U]
                        int B, int T, int U)
{
    const int idx = blockIdx.x * blockDim.x + threadIdx.x;
    if (idx >= B * U) return;
    const int b  = idx / U;
    const int uu = idx - b * U;

    const float uc = fminf(fmaxf(u[uu], 0.0f), 1.0f);
    float h = h0[(size_t)b * U + uu];

    float* p = P + (size_t)b * T * U + uu;
    const size_t strideU = (size_t)U;

    #pragma unroll 1
    for (int t = 0; t < T; t += 8) {
        float v[8];
        #pragma unroll
        for (int i = 0; i < 8; i++)
            v[i] = p[(size_t)(t + i) * strideU];
        #pragma unroll
        for (int i = 0; i < 8; i++) {
            h = fmaxf(fmaf(h, uc, v[i]), 0.0f);
            v[i] = h;
        }
        #pragma unroll
        for (int i = 0; i < 8; i++)
            p[(size_t)(t + i) * strideU] = v[i];
    }
}

extern "C" void kernel_launch(void* const* d_in, const int* in_sizes, int n_in,
                              void* d_out, int out_size)
{
    const float* x  = (const float*)d_in[0];  // [B,T,D]
    const float* h0 = (const float*)d_in[1];  // [B,U]
    const float* W  = (const float*)d_in[2];  // [D,U]
    const float* u  = (const float*)d_in[3];  // [U]
    const float* bb = (const float*)d_in[4];  // [U]
    float* out = (float*)d_out;               // [B,T,U]

    const int U = in_sizes[3];
    const int B = in_sizes[1] / U;
    const int D = in_sizes[2] / U;
    const int T = in_sizes[0] / (B * D);

    const int M = B * T;   // 32768
    const int N = U;       // 512
    const int K = D;       // 256

    dim3 gemmGrid(N / BN, M / BM);   // (4, 256)
    sgemm_bias_kernel<<<gemmGrid, 256>>>(x, W, bb, out, M, N, K);

    const int chains = B * U;        // 32768
    indrnn_scan_kernel<<<(chains + 255) / 256, 256>>>(out, h0, u, B, T, U);
}

// round 3
// speedup vs baseline: 2.2561x; 2.2561x over previous
#include <cuda_runtime.h>
#include <cuda_bf16.h>
#include <cstdint>

// ============================================================================
// IndRNN on GB300 (generic-target tensor path: mma.sync bf16, 3-pass split):
//   proj = x @ W + b      -> fp32 via split-bf16 HMMA, written into d_out
//   h_t = relu(proj_t + h_{t-1} * clip(u,0,1))  -> in-place pipelined scan
// Shapes: B=64, T=512, D(K)=256, U(N)=512, M=B*T=32768
// ============================================================================

#define U_DIM 512
#define K_DIM 256
#define MT 128
#define NT 128
#define KC 32
#define ROWB 80      // padded smem row stride in bytes (40 bf16) - conflict-free ldmatrix

// W transposed + split into bf16 hi/lo, [N][K] layout (k contiguous per row)
__device__ __nv_bfloat16 g_Wt_hi[U_DIM * K_DIM];
__device__ __nv_bfloat16 g_Wt_lo[U_DIM * K_DIM];

// ---------------------------------------------------------------- helpers
__device__ __forceinline__ uint32_t smem_u32(const void* p) {
    uint32_t a;
    asm("{ .reg .u64 t; cvta.to.shared.u64 t, %1; cvt.u32.u64 %0, t; }"
        : "=r"(a) : "l"(p));
    return a;
}
__device__ __forceinline__ void ldsm_x4(uint32_t* r, uint32_t addr) {
    asm volatile("ldmatrix.sync.aligned.m8n8.x4.shared.b16 {%0,%1,%2,%3}, [%4];"
                 : "=r"(r[0]), "=r"(r[1]), "=r"(r[2]), "=r"(r[3]) : "r"(addr));
}
__device__ __forceinline__ void mma_bf16(float* c, const uint32_t* a,
                                         uint32_t b0, uint32_t b1) {
    asm volatile(
        "mma.sync.aligned.m16n8k16.row.col.f32.bf16.bf16.f32 "
        "{%0,%1,%2,%3}, {%4,%5,%6,%7}, {%8,%9}, {%0,%1,%2,%3};"
        : "+f"(c[0]), "+f"(c[1]), "+f"(c[2]), "+f"(c[3])
        : "r"(a[0]), "r"(a[1]), "r"(a[2]), "r"(a[3]), "r"(b0), "r"(b1));
}
__device__ __forceinline__ uint32_t pack_bf2(__nv_bfloat16 a, __nv_bfloat16 b) {
    __nv_bfloat162 p(a, b);
    return *reinterpret_cast<uint32_t*>(&p);
}

// ---------------------------------------------------------------- W transpose+split
__global__ void wsplit_kernel(const float* __restrict__ W) {
    __shared__ float tile[32][33];
    const int n0 = blockIdx.x * 32, k0 = blockIdx.y * 32;
    const int tx = threadIdx.x, ty = threadIdx.y;   // 32 x 8
    #pragma unroll
    for (int i = 0; i < 32; i += 8)
        tile[ty + i][tx] = W[(size_t)(k0 + ty + i) * U_DIM + n0 + tx];
    __syncthreads();
    #pragma unroll
    for (int i = 0; i < 32; i += 8) {
        float v = tile[tx][ty + i];
        __nv_bfloat16 hi = __float2bfloat16(v);
        __nv_bfloat16 lo = __float2bfloat16(v - __bfloat162float(hi));
        size_t o = (size_t)(n0 + ty + i) * K_DIM + k0 + tx;
        g_Wt_hi[o] = hi;
        g_Wt_lo[o] = lo;
    }
}

// ---------------------------------------------------------------- HMMA GEMM
// 256 threads = 8 warps in 4(m) x 2(n) grid. Warp tile 32x64.
// Per warp: 2 m-tiles (m16) x 8 n-tiles (n8), fp32 acc = 64 regs.
__global__ __launch_bounds__(256, 2)
void gemm_mma_kernel(const float* __restrict__ A,     // [M, K] fp32
                     const float* __restrict__ bias,  // [N]
                     float* __restrict__ C)           // [M, U_DIM]
{
    __shared__ __nv_bfloat16 sAh[128 * 40];
    __shared__ __nv_bfloat16 sAl[128 * 40];
    __shared__ __nv_bfloat16 sBh[128 * 40];
    __shared__ __nv_bfloat16 sBl[128 * 40];

    const int tid  = threadIdx.x;
    const int lane = tid & 31;
    const int wid  = tid >> 5;
    const int wm   = wid & 3;         // warp m index (0-3)
    const int wn   = wid >> 2;        // warp n index (0-1)
    const int m0   = blockIdx.y * MT;
    const int n0   = blockIdx.x * NT;

    const uint32_t uAh = smem_u32(sAh), uAl = smem_u32(sAl);
    const uint32_t uBh = smem_u32(sBh), uBl = smem_u32(sBl);

    float acc[2][8][4];
    #pragma unroll
    for (int mt = 0; mt < 2; mt++)
        #pragma unroll
        for (int nt = 0; nt < 8; nt++)
            #pragma unroll
            for (int q = 0; q < 4; q++)
                acc[mt][nt][q] = 0.0f;

    // precomputed ldmatrix addresses (bytes)
    const uint32_t aOff = (uint32_t)((lane & 15) * ROWB + (lane >> 4) * 16);
    const uint32_t bOff = (uint32_t)(((lane & 7) + ((lane >> 4) & 1) * 8) * ROWB
                                     + ((lane >> 3) & 1) * 16);

    #pragma unroll 1
    for (int c = 0; c < K_DIM / KC; c++) {
        const int kg = c * KC;

        // ---- A tile: 128x32 fp32 -> split bf16 hi/lo, padded STS ----
        #pragma unroll
        for (int i = 0; i < 4; i++) {
            int f = i * 256 + tid;        // 0..1023
            int row = f >> 3, c4 = f & 7; // row 0..127, float4 col 0..7
            float4 v = *reinterpret_cast<const float4*>(
                A + (size_t)(m0 + row) * K_DIM + kg + c4 * 4);
            __nv_bfloat16 hx = __float2bfloat16(v.x), hy = __float2bfloat16(v.y);
            __nv_bfloat16 hz = __float2bfloat16(v.z), hw = __float2bfloat16(v.w);
            __nv_bfloat16 lx = __float2bfloat16(v.x - __bfloat162float(hx));
            __nv_bfloat16 ly = __float2bfloat16(v.y - __bfloat162float(hy));
            __nv_bfloat16 lz = __float2bfloat16(v.z - __bfloat162float(hz));
            __nv_bfloat16 lw = __float2bfloat16(v.w - __bfloat162float(hw));
            uint32_t off = (uint32_t)(row * ROWB + c4 * 8);
            asm volatile("st.shared.v2.b32 [%0], {%1, %2};"
                         :: "r"(uAh + off), "r"(pack_bf2(hx, hy)), "r"(pack_bf2(hz, hw)) : "memory");
            asm volatile("st.shared.v2.b32 [%0], {%1, %2};"
                         :: "r"(uAl + off), "r"(pack_bf2(lx, ly)), "r"(pack_bf2(lz, lw)) : "memory");
        }
        // ---- B tiles: bf16 hi/lo straight copy, padded STS ----
        #pragma unroll
        for (int i = 0; i < 4; i++) {
            int g = i * 256 + tid;            // 0..1023 ; first 512 = hi, rest = lo
            int hi = (g < 512);
            int gg = g & 511;
            int row = gg >> 2, c16 = gg & 3;  // row 0..127, uint4 col 0..3
            const __nv_bfloat16* src = (hi ? g_Wt_hi : g_Wt_lo)
                                       + (size_t)(n0 + row) * K_DIM + kg + c16 * 8;
            uint4 v = *reinterpret_cast<const uint4*>(src);
            uint32_t dst = (hi ? uBh : uBl) + (uint32_t)(row * ROWB + c16 * 16);
            asm volatile("st.shared.v4.b32 [%0], {%1,%2,%3,%4};"
                         :: "r"(dst), "r"(v.x), "r"(v.y), "r"(v.z), "r"(v.w) : "memory");
        }
        __syncthreads();

        // ---- compute: 2 k-steps of 16, 3 passes (hh, lh, hl) ----
        #pragma unroll
        for (int ks = 0; ks < 2; ks++) {
            const uint32_t kb = ks * 32;   // 16 bf16 = 32 bytes
            uint32_t ah[2][4], al[2][4];
            #pragma unroll
            for (int mt = 0; mt < 2; mt++) {
                uint32_t ra = (uint32_t)((wm * 32 + mt * 16) * ROWB) + aOff + kb;
                ldsm_x4(ah[mt], uAh + ra);
                ldsm_x4(al[mt], uAl + ra);
            }
            #pragma unroll
            for (int np = 0; np < 4; np++) {     // pairs of n-tiles
                uint32_t rb = (uint32_t)((wn * 64 + np * 16) * ROWB) + bOff + kb;
                uint32_t bh[4], bl[4];
                ldsm_x4(bh, uBh + rb);
                ldsm_x4(bl, uBl + rb);
                #pragma unroll
                for (int mt = 0; mt < 2; mt++) {
                    mma_bf16(acc[mt][np * 2 + 0], ah[mt], bh[0], bh[1]);
                    mma_bf16(acc[mt][np * 2 + 1], ah[mt], bh[2], bh[3]);
                    mma_bf16(acc[mt][np * 2 + 0], al[mt], bh[0], bh[1]);
                    mma_bf16(acc[mt][np * 2 + 1], al[mt], bh[2], bh[3]);
                    mma_bf16(acc[mt][np * 2 + 0], ah[mt], bl[0], bl[1]);
                    mma_bf16(acc[mt][np * 2 + 1], ah[mt], bl[2], bl[3]);
                }
            }
        }
        __syncthreads();
    }

    // ---- epilogue: + bias, fp32 stores ----
    const int colBase = n0 + wn * 64 + (lane & 3) * 2;
    const int rowBase = m0 + wm * 32 + (lane >> 2);
    #pragma unroll
    for (int nt = 0; nt < 8; nt++) {
        const int col = colBase + nt * 8;
        float2 bv = *reinterpret_cast<const float2*>(bias + col);
        #pragma unroll
        for (int mt = 0; mt < 2; mt++) {
            const int r = rowBase + mt * 16;
            float2 o0 = { acc[mt][nt][0] + bv.x, acc[mt][nt][1] + bv.y };
            float2 o1 = { acc[mt][nt][2] + bv.x, acc[mt][nt][3] + bv.y };
            *reinterpret_cast<float2*>(C + (size_t)r * U_DIM + col)       = o0;
            *reinterpret_cast<float2*>(C + (size_t)(r + 8) * U_DIM + col) = o1;
        }
    }
}

// ---------------------------------------------------------------- scan
// One thread per (b,u) chain; chunk=16, depth-2 register double buffering.
__global__ __launch_bounds__(256)
void indrnn_scan_kernel(float* __restrict__ P,        // [B,T,U] in-place
                        const float* __restrict__ h0, // [B,U]
                        const float* __restrict__ u,  // [U]
                        int B, int T, int U)
{
    const int idx = blockIdx.x * blockDim.x + threadIdx.x;
    if (idx >= B * U) return;
    const int b  = idx / U;
    const int uu = idx - b * U;

    const float uc = fminf(fmaxf(u[uu], 0.0f), 1.0f);
    float h = h0[(size_t)b * U + uu];

    float* p = P + (size_t)b * T * U + uu;
    const size_t sU = (size_t)U;

    float v0[16], v1[16];
    #pragma unroll
    for (int i = 0; i < 16; i++) v0[i] = p[(size_t)i * sU];
    #pragma unroll
    for (int i = 0; i < 16; i++) v1[i] = p[(size_t)(16 + i) * sU];

    #pragma unroll 1
    for (int t = 0; t < T; t += 32) {
        #pragma unroll
        for (int i = 0; i < 16; i++) {
            h = fmaxf(fmaf(h, uc, v0[i]), 0.0f);
            v0[i] = h;
        }
        #pragma unroll
        for (int i = 0; i < 16; i++)
            p[(size_t)(t + i) * sU] = v0[i];
        if (t + 32 < T) {
            #pragma unroll
            for (int i = 0; i < 16; i++)
                v0[i] = p[(size_t)(t + 32 + i) * sU];
        }
        #pragma unroll
        for (int i = 0; i < 16; i++) {
            h = fmaxf(fmaf(h, uc, v1[i]), 0.0f);
            v1[i] = h;
        }
        #pragma unroll
        for (int i = 0; i < 16; i++)
            p[(size_t)(t + 16 + i) * sU] = v1[i];
        if (t + 48 < T) {
            #pragma unroll
            for (int i = 0; i < 16; i++)
                v1[i] = p[(size_t)(t + 48 + i) * sU];
        }
    }
}

// ---------------------------------------------------------------- launch
extern "C" void kernel_launch(void* const* d_in, const int* in_sizes, int n_in,
                              void* d_out, int out_size)
{
    const float* x  = (const float*)d_in[0];  // [B,T,D]
    const float* h0 = (const float*)d_in[1];  // [B,U]
    const float* W  = (const float*)d_in[2];  // [D,U]
    const float* u  = (const float*)d_in[3];  // [U]
    const float* bb = (const float*)d_in[4];  // [U]
    float* out = (float*)d_out;               // [B,T,U]

    const int U = in_sizes[3];                // 512
    const int B = in_sizes[1] / U;            // 64
    const int D = in_sizes[2] / U;            // 256
    const int T = in_sizes[0] / (B * D);      // 512
    const int M = B * T;                      // 32768

    // 1) transpose + bf16-split W
    wsplit_kernel<<<dim3(U / 32, D / 32), dim3(32, 8)>>>(W);

    // 2) split-bf16 HMMA GEMM with fused bias
    dim3 gg(U / NT, M / MT);  // (4, 256)
    gemm_mma_kernel<<<gg, 256>>>(x, bb, out);

    // 3) in-place recurrence
    const int chains = B * U;  // 32768
    indrnn_scan_kernel<<<(chains + 255) / 256, 256>>>(out, h0, u, B, T, U);
}

// round 4
// speedup vs baseline: 2.7916x; 1.2374x over previous
#include <cuda_runtime.h>
#include <cuda_fp16.h>
#include <cstdint>

// ============================================================================
// IndRNN on GB300 (mma.sync fp16 2-pass split, double-buffered pipeline):
//   proj = x @ W + b  : x split to fp16 hi+lo (exact), W rounded to fp16 once.
//                       proj = Ah*W + Al*W, fp32 accum. err ~ 2^-11/sqrt(3).
//   h_t = relu(proj_t + h_{t-1} * clip(u,0,1)) : in-place chunked scan.
// Shapes: B=64, T=512, D(K)=256, U(N)=512, M=B*T=32768
// ============================================================================

#define U_DIM 512
#define K_DIM 256
#define MT 128
#define NT 128
#define KC 32
#define ROWB 80                 // 80 = 5*16: keeps ldmatrix 16B-aligned, staggers banks
#define STAGE (128 * ROWB)      // 10240 B per buffer
#define SMEM_BYTES (6 * STAGE)  // Ah,Al,B  x 2 stages

// W transposed to [N][K], rounded to fp16 once per launch
__device__ __half g_Wt[U_DIM * K_DIM];

// ---------------------------------------------------------------- helpers
__device__ __forceinline__ uint32_t smem_u32(const void* p) {
    uint32_t a;
    asm("{ .reg .u64 t; cvta.to.shared.u64 t, %1; cvt.u32.u64 %0, t; }"
        : "=r"(a) : "l"(p));
    return a;
}
__device__ __forceinline__ void ldsm_x4(uint32_t* r, uint32_t addr) {
    asm volatile("ldmatrix.sync.aligned.m8n8.x4.shared.b16 {%0,%1,%2,%3}, [%4];"
                 : "=r"(r[0]), "=r"(r[1]), "=r"(r[2]), "=r"(r[3]) : "r"(addr));
}
__device__ __forceinline__ void mma_f16(float* c, const uint32_t* a,
                                        uint32_t b0, uint32_t b1) {
    asm volatile(
        "mma.sync.aligned.m16n8k16.row.col.f32.f16.f16.f32 "
        "{%0,%1,%2,%3}, {%4,%5,%6,%7}, {%8,%9}, {%0,%1,%2,%3};"
        : "+f"(c[0]), "+f"(c[1]), "+f"(c[2]), "+f"(c[3])
        : "r"(a[0]), "r"(a[1]), "r"(a[2]), "r"(a[3]), "r"(b0), "r"(b1));
}
__device__ __forceinline__ void cp_async16(uint32_t dst, const void* src) {
    asm volatile("cp.async.cg.shared.global [%0], [%1], 16;"
                 :: "r"(dst), "l"(src) : "memory");
}
#define CP_COMMIT() asm volatile("cp.async.commit_group;" ::: "memory")
#define CP_WAIT0()  asm volatile("cp.async.wait_group 0;" ::: "memory")

__device__ __forceinline__ uint32_t pack_h2(__half a, __half b) {
    __half2 p(a, b);
    return *reinterpret_cast<uint32_t*>(&p);
}
// split float4 into fp16 hi/lo and store 8B each
__device__ __forceinline__ void sts_split4(float4 v, uint32_t dhi, uint32_t dlo) {
    __half hx = __float2half_rn(v.x), hy = __float2half_rn(v.y);
    __half hz = __float2half_rn(v.z), hw = __float2half_rn(v.w);
    __half lx = __float2half_rn(v.x - __half2float(hx));
    __half ly = __float2half_rn(v.y - __half2float(hy));
    __half lz = __float2half_rn(v.z - __half2float(hz));
    __half lw = __float2half_rn(v.w - __half2float(hw));
    asm volatile("st.shared.v2.b32 [%0], {%1, %2};"
                 :: "r"(dhi), "r"(pack_h2(hx, hy)), "r"(pack_h2(hz, hw)) : "memory");
    asm volatile("st.shared.v2.b32 [%0], {%1, %2};"
                 :: "r"(dlo), "r"(pack_h2(lx, ly)), "r"(pack_h2(lz, lw)) : "memory");
}

// ---------------------------------------------------------------- W transpose
__global__ void wsplit_kernel(const float* __restrict__ W) {
    __shared__ float tile[32][33];
    const int n0 = blockIdx.x * 32, k0 = blockIdx.y * 32;
    const int tx = threadIdx.x, ty = threadIdx.y;   // 32 x 8
    #pragma unroll
    for (int i = 0; i < 32; i += 8)
        tile[ty + i][tx] = W[(size_t)(k0 + ty + i) * U_DIM + n0 + tx];
    __syncthreads();
    #pragma unroll
    for (int i = 0; i < 32; i += 8)
        g_Wt[(size_t)(n0 + ty + i) * K_DIM + k0 + tx] =
            __float2half_rn(tile[tx][ty + i]);
}

// ---------------------------------------------------------------- HMMA GEMM
// 256 threads = 8 warps in 4(m) x 2(n). Warp tile 32x64.
// 2-stage pipeline: cp.async for B, reg-prefetch LDG + convert + STS for A.
__global__ __launch_bounds__(256, 1)
void gemm_mma_kernel(const float* __restrict__ A,     // [M, K] fp32
                     const float* __restrict__ bias,  // [N]
                     float* __restrict__ C)           // [M, U_DIM]
{
    extern __shared__ char smem[];
    const uint32_t sb = smem_u32(smem);

    const int tid  = threadIdx.x;
    const int lane = tid & 31;
    const int wid  = tid >> 5;
    const int wm   = wid & 3;
    const int wn   = wid >> 2;
    const int m0   = blockIdx.y * MT;
    const int n0   = blockIdx.x * NT;

    // stage s: Ah = sb + s*3*STAGE, Al = +STAGE, B = +2*STAGE
    float acc[2][8][4];
    #pragma unroll
    for (int mt = 0; mt < 2; mt++)
        #pragma unroll
        for (int nt = 0; nt < 8; nt++)
            #pragma unroll
            for (int q = 0; q < 4; q++)
                acc[mt][nt][q] = 0.0f;

    // A load mapping: 4 float4/thread: f=i*256+tid, row=f>>3, c4=f&7
    const int aRow[4] = { (0*256 + tid) >> 3, (1*256 + tid) >> 3,
                          (2*256 + tid) >> 3, (3*256 + tid) >> 3 };
    const int aC4 = tid & 7;
    // B copy mapping: 2 x 16B/thread: g=i*256+tid, row=g>>2, c16=g&3
    const int bRow[2] = { (0*256 + tid) >> 2, (1*256 + tid) >> 2 };
    const int bC16 = tid & 3;

    // ldmatrix lane offsets (bytes)
    const uint32_t aOff = (uint32_t)((lane & 15) * ROWB + (lane >> 4) * 16);
    const uint32_t bOff = (uint32_t)(((lane & 7) + ((lane >> 4) & 1) * 8) * ROWB
                                     + ((lane >> 3) & 1) * 16);

    float4 rA[4];

    // ---- prologue: chunk 0 ----
    #pragma unroll
    for (int i = 0; i < 4; i++)
        rA[i] = *reinterpret_cast<const float4*>(
            A + (size_t)(m0 + aRow[i]) * K_DIM + aC4 * 4);
    #pragma unroll
    for (int i = 0; i < 2; i++)
        cp_async16(sb + 2 * STAGE + (uint32_t)(bRow[i] * ROWB + bC16 * 16),
                   g_Wt + (size_t)(n0 + bRow[i]) * K_DIM + bC16 * 8);
    CP_COMMIT();
    #pragma unroll
    for (int i = 0; i < 4; i++) {
        uint32_t off = (uint32_t)(aRow[i] * ROWB + aC4 * 8);
        sts_split4(rA[i], sb + off, sb + STAGE + off);
    }

    #pragma unroll 1
    for (int c = 0; c < K_DIM / KC; c++) {
        const uint32_t base = (uint32_t)((c & 1) * 3 * STAGE);
        const uint32_t nbase = (uint32_t)(((c + 1) & 1) * 3 * STAGE);
        const int kn = (c + 1) * KC;

        // prefetch next A chunk into registers (before the wait)
        if (c < 7) {
            #pragma unroll
            for (int i = 0; i < 4; i++)
                rA[i] = *reinterpret_cast<const float4*>(
                    A + (size_t)(m0 + aRow[i]) * K_DIM + kn + aC4 * 4);
        }

        CP_WAIT0();
        __syncthreads();

        // kick next B cp.async
        if (c < 7) {
            #pragma unroll
            for (int i = 0; i < 2; i++)
                cp_async16(sb + nbase + 2 * STAGE
                               + (uint32_t)(bRow[i] * ROWB + bC16 * 16),
                           g_Wt + (size_t)(n0 + bRow[i]) * K_DIM + kn + bC16 * 8);
            CP_COMMIT();
        }

        // ---- compute current chunk: 2 k-steps of 16, 2 passes (Ah*B, Al*B) ----
        const uint32_t uAh = sb + base, uAl = sb + base + STAGE, uB = sb + base + 2 * STAGE;
        #pragma unroll
        for (int ks = 0; ks < 2; ks++) {
            const uint32_t kb = ks * 32;
            uint32_t ah[2][4], al[2][4];
            #pragma unroll
            for (int mt = 0; mt < 2; mt++) {
                uint32_t ra = (uint32_t)((wm * 32 + mt * 16) * ROWB) + aOff + kb;
                ldsm_x4(ah[mt], uAh + ra);
                ldsm_x4(al[mt], uAl + ra);
            }
            #pragma unroll
            for (int np = 0; np < 4; np++) {
                uint32_t rb = (uint32_t)((wn * 64 + np * 16) * ROWB) + bOff + kb;
                uint32_t bh[4];
                ldsm_x4(bh, uB + rb);
                #pragma unroll
                for (int mt = 0; mt < 2; mt++) {
                    mma_f16(acc[mt][np * 2 + 0], ah[mt], bh[0], bh[1]);
                    mma_f16(acc[mt][np * 2 + 1], ah[mt], bh[2], bh[3]);
                    mma_f16(acc[mt][np * 2 + 0], al[mt], bh[0], bh[1]);
                    mma_f16(acc[mt][np * 2 + 1], al[mt], bh[2], bh[3]);
                }
            }
        }

        // store next A into the other stage (targets buffers not read this iter)
        if (c < 7) {
            #pragma unroll
            for (int i = 0; i < 4; i++) {
                uint32_t off = (uint32_t)(aRow[i] * ROWB + aC4 * 8);
                sts_split4(rA[i], sb + nbase + off, sb + nbase + STAGE + off);
            }
        }
    }

    // ---- epilogue: + bias, fp32 stores ----
    const int colBase = n0 + wn * 64 + (lane & 3) * 2;
    const int rowBase = m0 + wm * 32 + (lane >> 2);
    #pragma unroll
    for (int nt = 0; nt < 8; nt++) {
        const int col = colBase + nt * 8;
        float2 bv = *reinterpret_cast<const float2*>(bias + col);
        #pragma unroll
        for (int mt = 0; mt < 2; mt++) {
            const int r = rowBase + mt * 16;
            float2 o0 = { acc[mt][nt][0] + bv.x, acc[mt][nt][1] + bv.y };
            float2 o1 = { acc[mt][nt][2] + bv.x, acc[mt][nt][3] + bv.y };
            *reinterpret_cast<float2*>(C + (size_t)r * U_DIM + col)       = o0;
            *reinterpret_cast<float2*>(C + (size_t)(r + 8) * U_DIM + col) = o1;
        }
    }
}

// ---------------------------------------------------------------- scan
__global__ __launch_bounds__(256)
void indrnn_scan_kernel(float* __restrict__ P,        // [B,T,U] in-place
                        const float* __restrict__ h0, // [B,U]
                        const float* __restrict__ u,  // [U]
                        int B, int T, int U)
{
    const int idx = blockIdx.x * blockDim.x + threadIdx.x;
    if (idx >= B * U) return;
    const int b  = idx / U;
    const int uu = idx - b * U;

    const float uc = fminf(fmaxf(u[uu], 0.0f), 1.0f);
    float h = h0[(size_t)b * U + uu];

    float* p = P + (size_t)b * T * U + uu;
    const size_t sU = (size_t)U;

    float v0[16], v1[16];
    #pragma unroll
    for (int i = 0; i < 16; i++) v0[i] = p[(size_t)i * sU];
    #pragma unroll
    for (int i = 0; i < 16; i++) v1[i] = p[(size_t)(16 + i) * sU];

    #pragma unroll 1
    for (int t = 0; t < T; t += 32) {
        #pragma unroll
        for (int i = 0; i < 16; i++) {
            h = fmaxf(fmaf(h, uc, v0[i]), 0.0f);
            v0[i] = h;
        }
        #pragma unroll
        for (int i = 0; i < 16; i++)
            p[(size_t)(t + i) * sU] = v0[i];
        if (t + 32 < T) {
            #pragma unroll
            for (int i = 0; i < 16; i++)
                v0[i] = p[(size_t)(t + 32 + i) * sU];
        }
        #pragma unroll
        for (int i = 0; i < 16; i++) {
            h = fmaxf(fmaf(h, uc, v1[i]), 0.0f);
            v1[i] = h;
        }
        #pragma unroll
        for (int i = 0; i < 16; i++)
            p[(size_t)(t + 16 + i) * sU] = v1[i];
        if (t + 48 < T) {
            #pragma unroll
            for (int i = 0; i < 16; i++)
                v1[i] = p[(size_t)(t + 48 + i) * sU];
        }
    }
}

// ---------------------------------------------------------------- launch
extern "C" void kernel_launch(void* const* d_in, const int* in_sizes, int n_in,
                              void* d_out, int out_size)
{
    const float* x  = (const float*)d_in[0];  // [B,T,D]
    const float* h0 = (const float*)d_in[1];  // [B,U]
    const float* W  = (const float*)d_in[2];  // [D,U]
    const float* u  = (const float*)d_in[3];  // [U]
    const float* bb = (const float*)d_in[4];  // [U]
    float* out = (float*)d_out;               // [B,T,U]

    const int U = in_sizes[3];                // 512
    const int B = in_sizes[1] / U;            // 64
    const int D = in_sizes[2] / U;            // 256
    const int T = in_sizes[0] / (B * D);      // 512
    const int M = B * T;                      // 32768

    // 1) transpose + fp16-round W
    wsplit_kernel<<<dim3(U / 32, D / 32), dim3(32, 8)>>>(W);

    // 2) fp16 2-pass HMMA GEMM with fused bias (pipelined)
    cudaFuncSetAttribute(gemm_mma_kernel,
                         cudaFuncAttributeMaxDynamicSharedMemorySize, SMEM_BYTES);
    dim3 gg(U / NT, M / MT);  // (4, 256)
    gemm_mma_kernel<<<gg, 256, SMEM_BYTES>>>(x, bb, out);

    // 3) in-place recurrence
    const int chains = B * U;  // 32768
    indrnn_scan_kernel<<<(chains + 255) / 256, 256>>>(out, h0, u, B, T, U);
}

// round 5
// speedup vs baseline: 3.7156x; 1.3310x over previous
#include <cuda_runtime.h>
#include <cuda_fp16.h>
#include <cstdint>

// ============================================================================
// IndRNN on GB300 (mma.sync fp16 single-pass, double-buffered pipeline):
//   proj = x @ W + b  : x and W rounded to fp16, fp32 accumulate.
//                       err ~ sqrt(2)*2^-11/sqrt(3) ~ 2.5e-4 << 1e-3.
//   h_t = relu(proj_t + h_{t-1} * clip(u,0,1)) : in-place ring-buffered scan.
// Shapes: B=64, T=512, D(K)=256, U(N)=512, M=B*T=32768
// ============================================================================

#define U_DIM 512
#define K_DIM 256
#define MT 128
#define NT 128
#define KC 32
#define ROWB 80                  // 5*16: 16B-aligned, conflict-free ldmatrix
#define ASTG (128 * ROWB)        // 10240 B
#define BSTG (128 * ROWB)        // 10240 B
#define STG  (ASTG + BSTG)       // per-stage
#define SMEM_BYTES (2 * STG)     // 40960 B

// W transposed to [N][K], rounded to fp16 once per launch
__device__ __half g_Wt[U_DIM * K_DIM];

// ---------------------------------------------------------------- helpers
__device__ __forceinline__ uint32_t smem_u32(const void* p) {
    uint32_t a;
    asm("{ .reg .u64 t; cvta.to.shared.u64 t, %1; cvt.u32.u64 %0, t; }"
        : "=r"(a) : "l"(p));
    return a;
}
__device__ __forceinline__ void ldsm_x4(uint32_t* r, uint32_t addr) {
    asm volatile("ldmatrix.sync.aligned.m8n8.x4.shared.b16 {%0,%1,%2,%3}, [%4];"
                 : "=r"(r[0]), "=r"(r[1]), "=r"(r[2]), "=r"(r[3]) : "r"(addr));
}
__device__ __forceinline__ void mma_f16(float* c, const uint32_t* a,
                                        uint32_t b0, uint32_t b1) {
    asm volatile(
        "mma.sync.aligned.m16n8k16.row.col.f32.f16.f16.f32 "
        "{%0,%1,%2,%3}, {%4,%5,%6,%7}, {%8,%9}, {%0,%1,%2,%3};"
        : "+f"(c[0]), "+f"(c[1]), "+f"(c[2]), "+f"(c[3])
        : "r"(a[0]), "r"(a[1]), "r"(a[2]), "r"(a[3]), "r"(b0), "r"(b1));
}
__device__ __forceinline__ void cp_async16(uint32_t dst, const void* src) {
    asm volatile("cp.async.cg.shared.global [%0], [%1], 16;"
                 :: "r"(dst), "l"(src) : "memory");
}
#define CP_COMMIT() asm volatile("cp.async.commit_group;" ::: "memory")
#define CP_WAIT0()  asm volatile("cp.async.wait_group 0;" ::: "memory")

__device__ __forceinline__ uint32_t pack_h2(__half a, __half b) {
    __half2 p(a, b);
    return *reinterpret_cast<uint32_t*>(&p);
}
// round float4 to fp16 and store 8B
__device__ __forceinline__ void sts_round4(float4 v, uint32_t dst) {
    __half hx = __float2half_rn(v.x), hy = __float2half_rn(v.y);
    __half hz = __float2half_rn(v.z), hw = __float2half_rn(v.w);
    asm volatile("st.shared.v2.b32 [%0], {%1, %2};"
                 :: "r"(dst), "r"(pack_h2(hx, hy)), "r"(pack_h2(hz, hw)) : "memory");
}

// ---------------------------------------------------------------- W transpose
__global__ void wsplit_kernel(const float* __restrict__ W) {
    __shared__ float tile[32][33];
    const int n0 = blockIdx.x * 32, k0 = blockIdx.y * 32;
    const int tx = threadIdx.x, ty = threadIdx.y;   // 32 x 8
    #pragma unroll
    for (int i = 0; i < 32; i += 8)
        tile[ty + i][tx] = W[(size_t)(k0 + ty + i) * U_DIM + n0 + tx];
    __syncthreads();
    #pragma unroll
    for (int i = 0; i < 32; i += 8)
        g_Wt[(size_t)(n0 + ty + i) * K_DIM + k0 + tx] =
            __float2half_rn(tile[tx][ty + i]);
}

// ---------------------------------------------------------------- HMMA GEMM
// 256 threads = 8 warps in 4(m) x 2(n). Warp tile 32x64.
// 2-stage pipeline: cp.async for B, reg-prefetch LDG + convert + STS for A.
__global__ __launch_bounds__(256, 2)
void gemm_mma_kernel(const float* __restrict__ A,     // [M, K] fp32
                     const float* __restrict__ bias,  // [N]
                     float* __restrict__ C)           // [M, U_DIM]
{
    extern __shared__ char smem[];
    const uint32_t sb = smem_u32(smem);

    const int tid  = threadIdx.x;
    const int lane = tid & 31;
    const int wid  = tid >> 5;
    const int wm   = wid & 3;
    const int wn   = wid >> 2;
    const int m0   = blockIdx.y * MT;
    const int n0   = blockIdx.x * NT;

    float acc[2][8][4];
    #pragma unroll
    for (int mt = 0; mt < 2; mt++)
        #pragma unroll
        for (int nt = 0; nt < 8; nt++)
            #pragma unroll
            for (int q = 0; q < 4; q++)
                acc[mt][nt][q] = 0.0f;

    // A load mapping: 4 float4/thread: f=i*256+tid, row=f>>3, c4=f&7
    const int aRow[4] = { (0*256 + tid) >> 3, (1*256 + tid) >> 3,
                          (2*256 + tid) >> 3, (3*256 + tid) >> 3 };
    const int aC4 = tid & 7;
    // B copy mapping: 2 x 16B/thread
    const int bRow[2] = { (0*256 + tid) >> 2, (1*256 + tid) >> 2 };
    const int bC16 = tid & 3;

    // ldmatrix lane offsets (bytes)
    const uint32_t aOff = (uint32_t)((lane & 15) * ROWB + (lane >> 4) * 16);
    const uint32_t bOff = (uint32_t)(((lane & 7) + ((lane >> 4) & 1) * 8) * ROWB
                                     + ((lane >> 3) & 1) * 16);

    float4 rA[4];

    // ---- prologue: chunk 0 ----
    #pragma unroll
    for (int i = 0; i < 4; i++)
        rA[i] = *reinterpret_cast<const float4*>(
            A + (size_t)(m0 + aRow[i]) * K_DIM + aC4 * 4);
    #pragma unroll
    for (int i = 0; i < 2; i++)
        cp_async16(sb + ASTG + (uint32_t)(bRow[i] * ROWB + bC16 * 16),
                   g_Wt + (size_t)(n0 + bRow[i]) * K_DIM + bC16 * 8);
    CP_COMMIT();
    #pragma unroll
    for (int i = 0; i < 4; i++)
        sts_round4(rA[i], sb + (uint32_t)(aRow[i] * ROWB + aC4 * 8));

    #pragma unroll 1
    for (int c = 0; c < K_DIM / KC; c++) {
        const uint32_t base  = (uint32_t)((c & 1) * STG);
        const uint32_t nbase = (uint32_t)(((c + 1) & 1) * STG);
        const int kn = (c + 1) * KC;

        // prefetch next A chunk into registers (before the wait)
        if (c < 7) {
            #pragma unroll
            for (int i = 0; i < 4; i++)
                rA[i] = *reinterpret_cast<const float4*>(
                    A + (size_t)(m0 + aRow[i]) * K_DIM + kn + aC4 * 4);
        }

        CP_WAIT0();
        __syncthreads();

        // kick next B cp.async
        if (c < 7) {
            #pragma unroll
            for (int i = 0; i < 2; i++)
                cp_async16(sb + nbase + ASTG
                               + (uint32_t)(bRow[i] * ROWB + bC16 * 16),
                           g_Wt + (size_t)(n0 + bRow[i]) * K_DIM + kn + bC16 * 8);
            CP_COMMIT();
        }

        // ---- compute current chunk: 2 k-steps of 16, single fp16 pass ----
        const uint32_t uA = sb + base, uB = sb + base + ASTG;
        #pragma unroll
        for (int ks = 0; ks < 2; ks++) {
            const uint32_t kb = ks * 32;
            uint32_t ah[2][4];
            #pragma unroll
            for (int mt = 0; mt < 2; mt++)
                ldsm_x4(ah[mt], uA + (uint32_t)((wm * 32 + mt * 16) * ROWB) + aOff + kb);
            #pragma unroll
            for (int np = 0; np < 4; np++) {
                uint32_t bh[4];
                ldsm_x4(bh, uB + (uint32_t)((wn * 64 + np * 16) * ROWB) + bOff + kb);
                #pragma unroll
                for (int mt = 0; mt < 2; mt++) {
                    mma_f16(acc[mt][np * 2 + 0], ah[mt], bh[0], bh[1]);
                    mma_f16(acc[mt][np * 2 + 1], ah[mt], bh[2], bh[3]);
                }
            }
        }

        // store next A into the other stage
        if (c < 7) {
            #pragma unroll
            for (int i = 0; i < 4; i++)
                sts_round4(rA[i], sb + nbase + (uint32_t)(aRow[i] * ROWB + aC4 * 8));
        }
    }

    // ---- epilogue: + bias, fp32 stores ----
    const int colBase = n0 + wn * 64 + (lane & 3) * 2;
    const int rowBase = m0 + wm * 32 + (lane >> 2);
    #pragma unroll
    for (int nt = 0; nt < 8; nt++) {
        const int col = colBase + nt * 8;
        float2 bv = *reinterpret_cast<const float2*>(bias + col);
        #pragma unroll
        for (int mt = 0; mt < 2; mt++) {
            const int r = rowBase + mt * 16;
            float2 o0 = { acc[mt][nt][0] + bv.x, acc[mt][nt][1] + bv.y };
            float2 o1 = { acc[mt][nt][2] + bv.x, acc[mt][nt][3] + bv.y };
            *reinterpret_cast<float2*>(C + (size_t)r * U_DIM + col)       = o0;
            *reinterpret_cast<float2*>(C + (size_t)(r + 8) * U_DIM + col) = o1;
        }
    }
}

// ---------------------------------------------------------------- scan
// One thread per (b,u) chain. 4-buffer ring of 16-chunks; loads issued 2
// chunks (~270 cyc) ahead of consumption to cover L2 latency at low occ.
__global__ __launch_bounds__(256)
void indrnn_scan_kernel(float* __restrict__ P,        // [B,T,U] in-place
                        const float* __restrict__ h0, // [B,U]
                        const float* __restrict__ u,  // [U]
                        int B, int T, int U)
{
    const int idx = blockIdx.x * blockDim.x + threadIdx.x;
    if (idx >= B * U) return;
    const int b  = idx / U;
    const int uu = idx - b * U;

    const float uc = fminf(fmaxf(u[uu], 0.0f), 1.0f);
    float h = h0[(size_t)b * U + uu];

    float* p = P + (size_t)b * T * U + uu;
    const size_t sU = (size_t)U;
    const int NCH = T / 16;    // 32 chunks

    float v0[16], v1[16], v2[16], v3[16];

#define LOADC(buf, ch)                                            \
    { const int t0 = (ch) * 16;                                   \
      _Pragma("unroll")                                           \
      for (int i = 0; i < 16; i++) buf[i] = p[(size_t)(t0 + i) * sU]; }
#define STEPC(buf, ch)                                            \
    { const int t0 = (ch) * 16;                                   \
      _Pragma("unroll")                                           \
      for (int i = 0; i < 16; i++) {                              \
          h = fmaxf(fmaf(h, uc, buf[i]), 0.0f);                   \
          buf[i] = h;                                             \
      }                                                           \
      _Pragma("unroll")                                           \
      for (int i = 0; i < 16; i++) p[(size_t)(t0 + i) * sU] = buf[i]; }

    LOADC(v0, 0)
    LOADC(v1, 1)

    #pragma unroll 1
    for (int cBase = 0; cBase < NCH; cBase += 4) {
        if (cBase + 2 < NCH) LOADC(v2, cBase + 2)
        STEPC(v0, cBase)
        if (cBase + 3 < NCH) LOADC(v3, cBase + 3)
        STEPC(v1, cBase + 1)
        if (cBase + 4 < NCH) LOADC(v0, cBase + 4)
        if (cBase + 2 < NCH) STEPC(v2, cBase + 2)
        if (cBase + 5 < NCH) LOADC(v1, cBase + 5)
        if (cBase + 3 < NCH) STEPC(v3, cBase + 3)
    }
#undef LOADC
#undef STEPC
}

// ---------------------------------------------------------------- launch
extern "C" void kernel_launch(void* const* d_in, const int* in_sizes, int n_in,
                              void* d_out, int out_size)
{
    const float* x  = (const float*)d_in[0];  // [B,T,D]
    const float* h0 = (const float*)d_in[1];  // [B,U]
    const float* W  = (const float*)d_in[2];  // [D,U]
    const float* u  = (const float*)d_in[3];  // [U]
    const float* bb = (const float*)d_in[4];  // [U]
    float* out = (float*)d_out;               // [B,T,U]

    const int U = in_sizes[3];                // 512
    const int B = in_sizes[1] / U;            // 64
    const int D = in_sizes[2] / U;            // 256
    const int T = in_sizes[0] / (B * D);      // 512
    const int M = B * T;                      // 32768

    // 1) transpose + fp16-round W
    wsplit_kernel<<<dim3(U / 32, D / 32), dim3(32, 8)>>>(W);

    // 2) fp16 single-pass HMMA GEMM with fused bias (pipelined, 2 CTAs/SM)
    cudaFuncSetAttribute(gemm_mma_kernel,
                         cudaFuncAttributeMaxDynamicSharedMemorySize, SMEM_BYTES);
    dim3 gg(U / NT, M / MT);  // (4, 256)
    gemm_mma_kernel<<<gg, 256, SMEM_BYTES>>>(x, bb, out);

    // 3) in-place recurrence
    const int chains = B * U;  // 32768
    indrnn_scan_kernel<<<(chains + 255) / 256, 256>>>(out, h0, u, B, T, U);
}

// round 6
// speedup vs baseline: 4.2581x; 1.1460x over previous
#include <cuda_runtime.h>
#include <cuda_fp16.h>
#include <cstdint>

// ============================================================================
// IndRNN on GB300 — FUSED GEMM + scan:
//   Each CTA owns (n-block of 128, batch b). Processes the 4 t-chunks of 128
//   sequentially: HMMA GEMM tile -> dump acc(+bias) to smem -> scan 128 steps
//   (h carried in registers across chunks) -> coalesced STG. The intermediate
//   proj never touches global memory.
//   x,W in fp16 (single pass), fp32 accumulate: rel_err ~ 2.4e-4 << 1e-3.
// Shapes: B=64, T=512, D(K)=256, U(N)=512, M=B*T=32768
// ============================================================================

#define U_DIM 512
#define K_DIM 256
#define T_DIM 512
#define MT 128
#define NT 128
#define KC 32
#define ROWB 80                  // 5*16: 16B-aligned, conflict-free ldmatrix
#define ASTG (128 * ROWB)        // 10240 B
#define STG_B (2 * ASTG)         // per-stage: A + B
#define SCROW 132                // scan buffer row stride (floats), pad vs 128
#define SCBYTES (128 * SCROW * 4)            // 67584
#define SMEM_BYTES (SCBYTES)                 // stages (40960) overlay scanbuf

// W transposed to [N][K], rounded to fp16 once per launch
__device__ __half g_Wt[U_DIM * K_DIM];

// ---------------------------------------------------------------- helpers
__device__ __forceinline__ uint32_t smem_u32(const void* p) {
    uint32_t a;
    asm("{ .reg .u64 t; cvta.to.shared.u64 t, %1; cvt.u32.u64 %0, t; }"
        : "=r"(a) : "l"(p));
    return a;
}
__device__ __forceinline__ void ldsm_x4(uint32_t* r, uint32_t addr) {
    asm volatile("ldmatrix.sync.aligned.m8n8.x4.shared.b16 {%0,%1,%2,%3}, [%4];"
                 : "=r"(r[0]), "=r"(r[1]), "=r"(r[2]), "=r"(r[3]) : "r"(addr));
}
__device__ __forceinline__ void mma_f16(float* c, const uint32_t* a,
                                        uint32_t b0, uint32_t b1) {
    asm volatile(
        "mma.sync.aligned.m16n8k16.row.col.f32.f16.f16.f32 "
        "{%0,%1,%2,%3}, {%4,%5,%6,%7}, {%8,%9}, {%0,%1,%2,%3};"
        : "+f"(c[0]), "+f"(c[1]), "+f"(c[2]), "+f"(c[3])
        : "r"(a[0]), "r"(a[1]), "r"(a[2]), "r"(a[3]), "r"(b0), "r"(b1));
}
__device__ __forceinline__ void cp_async16(uint32_t dst, const void* src) {
    asm volatile("cp.async.cg.shared.global [%0], [%1], 16;"
                 :: "r"(dst), "l"(src) : "memory");
}
#define CP_COMMIT() asm volatile("cp.async.commit_group;" ::: "memory")
#define CP_WAIT0()  asm volatile("cp.async.wait_group 0;" ::: "memory")

__device__ __forceinline__ uint32_t pack_h2(__half a, __half b) {
    __half2 p(a, b);
    return *reinterpret_cast<uint32_t*>(&p);
}
__device__ __forceinline__ void sts_round4(float4 v, uint32_t dst) {
    __half hx = __float2half_rn(v.x), hy = __float2half_rn(v.y);
    __half hz = __float2half_rn(v.z), hw = __float2half_rn(v.w);
    asm volatile("st.shared.v2.b32 [%0], {%1, %2};"
                 :: "r"(dst), "r"(pack_h2(hx, hy)), "r"(pack_h2(hz, hw)) : "memory");
}

// ---------------------------------------------------------------- W transpose
__global__ void wsplit_kernel(const float* __restrict__ W) {
    __shared__ float tile[32][33];
    const int n0 = blockIdx.x * 32, k0 = blockIdx.y * 32;
    const int tx = threadIdx.x, ty = threadIdx.y;   // 32 x 8
    #pragma unroll
    for (int i = 0; i < 32; i += 8)
        tile[ty + i][tx] = W[(size_t)(k0 + ty + i) * U_DIM + n0 + tx];
    __syncthreads();
    #pragma unroll
    for (int i = 0; i < 32; i += 8)
        g_Wt[(size_t)(n0 + ty + i) * K_DIM + k0 + tx] =
            __float2half_rn(tile[tx][ty + i]);
}

// ---------------------------------------------------------------- fused kernel
// 256 threads = 8 warps in 4(m) x 2(n). Warp tile 32x64.
__global__ __launch_bounds__(256, 2)
void indrnn_fused_kernel(const float* __restrict__ A,     // x [M, K] fp32
                         const float* __restrict__ bias,  // [N]
                         const float* __restrict__ h0g,   // [B, U]
                         const float* __restrict__ ug,    // [U]
                         float* __restrict__ C)           // out [M, U_DIM]
{
    extern __shared__ char smem[];
    const uint32_t sb = smem_u32(smem);
    float* const scf = reinterpret_cast<float*>(smem);    // scan buffer view

    const int tid  = threadIdx.x;
    const int lane = tid & 31;
    const int wid  = tid >> 5;
    const int wm   = wid & 3;
    const int wn   = wid >> 2;
    const int n0   = blockIdx.x * NT;
    const int b    = blockIdx.y;
    const int mB   = b * T_DIM;          // first row of this batch

    // scan state (threads 0..127 each own one n-column)
    float h = 0.0f, uc = 0.0f;
    if (tid < 128) {
        uc = fminf(fmaxf(ug[n0 + tid], 0.0f), 1.0f);
        h  = h0g[(size_t)b * U_DIM + n0 + tid];
    }

    // A load mapping: 4 float4/thread
    const int aRow[4] = { (0*256 + tid) >> 3, (1*256 + tid) >> 3,
                          (2*256 + tid) >> 3, (3*256 + tid) >> 3 };
    const int aC4 = tid & 7;
    // B copy mapping: 2 x 16B/thread
    const int bRow[2] = { (0*256 + tid) >> 2, (1*256 + tid) >> 2 };
    const int bC16 = tid & 3;
    // ldmatrix lane offsets (bytes)
    const uint32_t aOff = (uint32_t)((lane & 15) * ROWB + (lane >> 4) * 16);
    const uint32_t bOff = (uint32_t)(((lane & 7) + ((lane >> 4) & 1) * 8) * ROWB
                                     + ((lane >> 3) & 1) * 16);
    // dump/epilogue fragment coords
    const int colBase = wn * 64 + (lane & 3) * 2;   // n_local
    const int rowBase = wm * 32 + (lane >> 2);      // t_local

    #pragma unroll 1
    for (int tc = 0; tc < T_DIM / MT; tc++) {
        const int m0 = mB + tc * MT;

        float acc[2][8][4];
        #pragma unroll
        for (int mt = 0; mt < 2; mt++)
            #pragma unroll
            for (int nt = 0; nt < 8; nt++)
                #pragma unroll
                for (int q = 0; q < 4; q++)
                    acc[mt][nt][q] = 0.0f;

        float4 rA[4];
        // ---- prologue: chunk 0 ----
        #pragma unroll
        for (int i = 0; i < 4; i++)
            rA[i] = *reinterpret_cast<const float4*>(
                A + (size_t)(m0 + aRow[i]) * K_DIM + aC4 * 4);
        #pragma unroll
        for (int i = 0; i < 2; i++)
            cp_async16(sb + ASTG + (uint32_t)(bRow[i] * ROWB + bC16 * 16),
                       g_Wt + (size_t)(n0 + bRow[i]) * K_DIM + bC16 * 8);
        CP_COMMIT();
        #pragma unroll
        for (int i = 0; i < 4; i++)
            sts_round4(rA[i], sb + (uint32_t)(aRow[i] * ROWB + aC4 * 8));

        #pragma unroll 1
        for (int c = 0; c < K_DIM / KC; c++) {
            const uint32_t base  = (uint32_t)((c & 1) * STG_B);
            const uint32_t nbase = (uint32_t)(((c + 1) & 1) * STG_B);
            const int kn = (c + 1) * KC;

            if (c < 7) {
                #pragma unroll
                for (int i = 0; i < 4; i++)
                    rA[i] = *reinterpret_cast<const float4*>(
                        A + (size_t)(m0 + aRow[i]) * K_DIM + kn + aC4 * 4);
            }

            CP_WAIT0();
            __syncthreads();

            if (c < 7) {
                #pragma unroll
                for (int i = 0; i < 2; i++)
                    cp_async16(sb + nbase + ASTG
                                   + (uint32_t)(bRow[i] * ROWB + bC16 * 16),
                               g_Wt + (size_t)(n0 + bRow[i]) * K_DIM + kn + bC16 * 8);
                CP_COMMIT();
            }

            const uint32_t uA = sb + base, uB = sb + base + ASTG;
            #pragma unroll
            for (int ks = 0; ks < 2; ks++) {
                const uint32_t kb = ks * 32;
                uint32_t ah[2][4];
                #pragma unroll
                for (int mt = 0; mt < 2; mt++)
                    ldsm_x4(ah[mt], uA + (uint32_t)((wm * 32 + mt * 16) * ROWB) + aOff + kb);
                #pragma unroll
                for (int np = 0; np < 4; np++) {
                    uint32_t bh[4];
                    ldsm_x4(bh, uB + (uint32_t)((wn * 64 + np * 16) * ROWB) + bOff + kb);
                    #pragma unroll
                    for (int mt = 0; mt < 2; mt++) {
                        mma_f16(acc[mt][np * 2 + 0], ah[mt], bh[0], bh[1]);
                        mma_f16(acc[mt][np * 2 + 1], ah[mt], bh[2], bh[3]);
                    }
                }
            }

            if (c < 7) {
                #pragma unroll
                for (int i = 0; i < 4; i++)
                    sts_round4(rA[i], sb + nbase + (uint32_t)(aRow[i] * ROWB + aC4 * 8));
            }
        }
        __syncthreads();   // all ldsm reads of stage buffers done (aliased below)

        // ---- dump acc (+bias) into scan buffer [t_local][n_local] ----
        #pragma unroll
        for (int nt = 0; nt < 8; nt++) {
            const int col = colBase + nt * 8;
            float2 bv = *reinterpret_cast<const float2*>(bias + n0 + col);
            #pragma unroll
            for (int mt = 0; mt < 2; mt++) {
                const int r = rowBase + mt * 16;
                float2 o0 = { acc[mt][nt][0] + bv.x, acc[mt][nt][1] + bv.y };
                float2 o1 = { acc[mt][nt][2] + bv.x, acc[mt][nt][3] + bv.y };
                *reinterpret_cast<float2*>(scf + (size_t)r * SCROW + col)       = o0;
                *reinterpret_cast<float2*>(scf + (size_t)(r + 8) * SCROW + col) = o1;
            }
        }
        __syncthreads();

        // ---- scan 128 timesteps in smem (threads 0..127, one column each) ----
        if (tid < 128) {
            #pragma unroll
            for (int t = 0; t < MT; t += 8) {
                float v[8];
                #pragma unroll
                for (int i = 0; i < 8; i++)
                    v[i] = scf[(size_t)(t + i) * SCROW + tid];
                #pragma unroll
                for (int i = 0; i < 8; i++) {
                    h = fmaxf(fmaf(h, uc, v[i]), 0.0f);
                    v[i] = h;
                }
                #pragma unroll
                for (int i = 0; i < 8; i++)
                    scf[(size_t)(t + i) * SCROW + tid] = v[i];
            }
        }
        __syncthreads();

        // ---- coalesced store of the scanned tile ----
        #pragma unroll
        for (int i = 0; i < 16; i++) {
            int idx = i * 256 + tid;        // float4 index, 0..4095
            int r = idx >> 5, c4 = idx & 31;
            float4 v = *reinterpret_cast<const float4*>(scf + (size_t)r * SCROW + c4 * 4);
            *reinterpret_cast<float4*>(C + (size_t)(m0 + r) * U_DIM + n0 + c4 * 4) = v;
        }
        __syncthreads();   // before next tchunk reuses aliased smem
    }
}

// ---------------------------------------------------------------- launch
extern "C" void kernel_launch(void* const* d_in, const int* in_sizes, int n_in,
                              void* d_out, int out_size)
{
    const float* x  = (const float*)d_in[0];  // [B,T,D]
    const float* h0 = (const float*)d_in[1];  // [B,U]
    const float* W  = (const float*)d_in[2];  // [D,U]
    const float* u  = (const float*)d_in[3];  // [U]
    const float* bb = (const float*)d_in[4];  // [U]
    float* out = (float*)d_out;               // [B,T,U]

    const int U = in_sizes[3];                // 512
    const int B = in_sizes[1] / U;            // 64
    const int D = in_sizes[2] / U;            // 256

    // 1) transpose + fp16-round W
    wsplit_kernel<<<dim3(U / 32, D / 32), dim3(32, 8)>>>(W);

    // 2) fused GEMM + scan
    cudaFuncSetAttribute(indrnn_fused_kernel,
                         cudaFuncAttributeMaxDynamicSharedMemorySize, SMEM_BYTES);
    dim3 gg(U / NT, B);   // (4, 64) = 256 CTAs, single wave at occ 2
    indrnn_fused_kernel<<<gg, 256, SMEM_BYTES>>>(x, bb, h0, u, out);
}

// round 7
// speedup vs baseline: 4.4275x; 1.0398x over previous
#include <cuda_runtime.h>
#include <cuda_fp16.h>
#include <cstdint>

// ============================================================================
// IndRNN on GB300 — FUSED GEMM + scan, tile-level software pipeline:
//   Each CTA owns (n-block of 128, batch b); 4 sequential t-chunks of 128.
//   Per tile: HMMA GEMM -> (prefetch next tile) -> dump acc(+bias) to smem ->
//   scan 128 steps, STG results DIRECTLY to gmem (no smem write-back).
//   Stage buffers and scan buffer are disjoint (106KB smem, occ 2).
//   x,W in fp16 single pass, fp32 accumulate: rel_err ~ 2.4e-4.
// Shapes: B=64, T=512, D(K)=256, U(N)=512, M=B*T=32768
// ============================================================================

#define U_DIM 512
#define K_DIM 256
#define T_DIM 512
#define MT 128
#define NT 128
#define KC 32
#define ROWB 80                    // 5*16: 16B-aligned, conflict-free ldmatrix
#define ASTG (128 * ROWB)          // 10240 B
#define STG_B (2 * ASTG)           // per-stage: A + B
#define STAGES_BYTES (2 * STG_B)   // 40960 B
#define SCROW 132                  // scan buffer row stride (floats)
#define SCBYTES (128 * SCROW * 4)  // 67584 B
#define SMEM_BYTES (STAGES_BYTES + SCBYTES)   // 108544 B, occ 2 -> 212KB/SM

// W transposed to [N][K], rounded to fp16 once per launch
__device__ __half g_Wt[U_DIM * K_DIM];

// ---------------------------------------------------------------- helpers
__device__ __forceinline__ uint32_t smem_u32(const void* p) {
    uint32_t a;
    asm("{ .reg .u64 t; cvta.to.shared.u64 t, %1; cvt.u32.u64 %0, t; }"
        : "=r"(a) : "l"(p));
    return a;
}
__device__ __forceinline__ void ldsm_x4(uint32_t* r, uint32_t addr) {
    asm volatile("ldmatrix.sync.aligned.m8n8.x4.shared.b16 {%0,%1,%2,%3}, [%4];"
                 : "=r"(r[0]), "=r"(r[1]), "=r"(r[2]), "=r"(r[3]) : "r"(addr));
}
__device__ __forceinline__ void mma_f16(float* c, const uint32_t* a,
                                        uint32_t b0, uint32_t b1) {
    asm volatile(
        "mma.sync.aligned.m16n8k16.row.col.f32.f16.f16.f32 "
        "{%0,%1,%2,%3}, {%4,%5,%6,%7}, {%8,%9}, {%0,%1,%2,%3};"
        : "+f"(c[0]), "+f"(c[1]), "+f"(c[2]), "+f"(c[3])
        : "r"(a[0]), "r"(a[1]), "r"(a[2]), "r"(a[3]), "r"(b0), "r"(b1));
}
__device__ __forceinline__ void cp_async16(uint32_t dst, const void* src) {
    asm volatile("cp.async.cg.shared.global [%0], [%1], 16;"
                 :: "r"(dst), "l"(src) : "memory");
}
#define CP_COMMIT() asm volatile("cp.async.commit_group;" ::: "memory")
#define CP_WAIT0()  asm volatile("cp.async.wait_group 0;" ::: "memory")

__device__ __forceinline__ uint32_t pack_h2(__half a, __half b) {
    __half2 p(a, b);
    return *reinterpret_cast<uint32_t*>(&p);
}
__device__ __forceinline__ void sts_round4(float4 v, uint32_t dst) {
    __half hx = __float2half_rn(v.x), hy = __float2half_rn(v.y);
    __half hz = __float2half_rn(v.z), hw = __float2half_rn(v.w);
    asm volatile("st.shared.v2.b32 [%0], {%1, %2};"
                 :: "r"(dst), "r"(pack_h2(hx, hy)), "r"(pack_h2(hz, hw)) : "memory");
}

// ---------------------------------------------------------------- W transpose
__global__ void wsplit_kernel(const float* __restrict__ W) {
    __shared__ float tile[32][33];
    const int n0 = blockIdx.x * 32, k0 = blockIdx.y * 32;
    const int tx = threadIdx.x, ty = threadIdx.y;   // 32 x 8
    #pragma unroll
    for (int i = 0; i < 32; i += 8)
        tile[ty + i][tx] = W[(size_t)(k0 + ty + i) * U_DIM + n0 + tx];
    __syncthreads();
    #pragma unroll
    for (int i = 0; i < 32; i += 8)
        g_Wt[(size_t)(n0 + ty + i) * K_DIM + k0 + tx] =
            __float2half_rn(tile[tx][ty + i]);
}

// ---------------------------------------------------------------- fused kernel
// 256 threads = 8 warps in 4(m) x 2(n). Warp tile 32x64.
__global__ __launch_bounds__(256, 2)
void indrnn_fused_kernel(const float* __restrict__ A,     // x [M, K] fp32
                         const float* __restrict__ bias,  // [N]
                         const float* __restrict__ h0g,   // [B, U]
                         const float* __restrict__ ug,    // [U]
                         float* __restrict__ C)           // out [M, U_DIM]
{
    extern __shared__ char smem[];
    const uint32_t sb = smem_u32(smem);                       // stage buffers
    float* const scf = reinterpret_cast<float*>(smem + STAGES_BYTES); // scan buf

    const int tid  = threadIdx.x;
    const int lane = tid & 31;
    const int wid  = tid >> 5;
    const int wm   = wid & 3;
    const int wn   = wid >> 2;
    const int n0   = blockIdx.x * NT;
    const int b    = blockIdx.y;
    const int mB   = b * T_DIM;

    // scan state (threads 0..127 each own one n-column)
    float h = 0.0f, uc = 0.0f;
    if (tid < 128) {
        uc = fminf(fmaxf(ug[n0 + tid], 0.0f), 1.0f);
        h  = h0g[(size_t)b * U_DIM + n0 + tid];
    }

    // A load mapping: 4 float4/thread
    const int aRow[4] = { (0*256 + tid) >> 3, (1*256 + tid) >> 3,
                          (2*256 + tid) >> 3, (3*256 + tid) >> 3 };
    const int aC4 = tid & 7;
    // B copy mapping: 2 x 16B/thread
    const int bRow[2] = { (0*256 + tid) >> 2, (1*256 + tid) >> 2 };
    const int bC16 = tid & 3;
    // ldmatrix lane offsets
    const uint32_t aOff = (uint32_t)((lane & 15) * ROWB + (lane >> 4) * 16);
    const uint32_t bOff = (uint32_t)(((lane & 7) + ((lane >> 4) & 1) * 8) * ROWB
                                     + ((lane >> 3) & 1) * 16);
    // fragment coords for dump
    const int colBase = wn * 64 + (lane & 3) * 2;   // n_local
    const int rowBase = wm * 32 + (lane >> 2);      // t_local

    float4 rA[4];

    // ---- prologue for tile 0, chunk 0 ----
    #pragma unroll
    for (int i = 0; i < 4; i++)
        rA[i] = *reinterpret_cast<const float4*>(
            A + (size_t)(mB + aRow[i]) * K_DIM + aC4 * 4);
    #pragma unroll
    for (int i = 0; i < 2; i++)
        cp_async16(sb + ASTG + (uint32_t)(bRow[i] * ROWB + bC16 * 16),
                   g_Wt + (size_t)(n0 + bRow[i]) * K_DIM + bC16 * 8);
    CP_COMMIT();
    #pragma unroll
    for (int i = 0; i < 4; i++)
        sts_round4(rA[i], sb + (uint32_t)(aRow[i] * ROWB + aC4 * 8));

    #pragma unroll 1
    for (int tc = 0; tc < T_DIM / MT; tc++) {
        const int m0 = mB + tc * MT;

        float acc[2][8][4];
        #pragma unroll
        for (int mt = 0; mt < 2; mt++)
            #pragma unroll
            for (int nt = 0; nt < 8; nt++)
                #pragma unroll
                for (int q = 0; q < 4; q++)
                    acc[mt][nt][q] = 0.0f;

        #pragma unroll 1
        for (int c = 0; c < K_DIM / KC; c++) {
            const uint32_t base  = (uint32_t)((c & 1) * STG_B);
            const uint32_t nbase = (uint32_t)(((c + 1) & 1) * STG_B);
            const int kn = (c + 1) * KC;

            if (c < 7) {
                #pragma unroll
                for (int i = 0; i < 4; i++)
                    rA[i] = *reinterpret_cast<const float4*>(
                        A + (size_t)(m0 + aRow[i]) * K_DIM + kn + aC4 * 4);
            }

            CP_WAIT0();
            __syncthreads();

            if (c < 7) {
                #pragma unroll
                for (int i = 0; i < 2; i++)
                    cp_async16(sb + nbase + ASTG
                                   + (uint32_t)(bRow[i] * ROWB + bC16 * 16),
                               g_Wt + (size_t)(n0 + bRow[i]) * K_DIM + kn + bC16 * 8);
                CP_COMMIT();
            }

            const uint32_t uA = sb + base, uB = sb + base + ASTG;
            #pragma unroll
            for (int ks = 0; ks < 2; ks++) {
                const uint32_t kb = ks * 32;
                uint32_t ah[2][4];
                #pragma unroll
                for (int mt = 0; mt < 2; mt++)
                    ldsm_x4(ah[mt], uA + (uint32_t)((wm * 32 + mt * 16) * ROWB) + aOff + kb);
                #pragma unroll
                for (int np = 0; np < 4; np++) {
                    uint32_t bh[4];
                    ldsm_x4(bh, uB + (uint32_t)((wn * 64 + np * 16) * ROWB) + bOff + kb);
                    #pragma unroll
                    for (int mt = 0; mt < 2; mt++) {
                        mma_f16(acc[mt][np * 2 + 0], ah[mt], bh[0], bh[1]);
                        mma_f16(acc[mt][np * 2 + 1], ah[mt], bh[2], bh[3]);
                    }
                }
            }

            if (c < 7) {
                #pragma unroll
                for (int i = 0; i < 4; i++)
                    sts_round4(rA[i], sb + nbase + (uint32_t)(aRow[i] * ROWB + aC4 * 8));
            }
        }

        // ---- prefetch NEXT tile (chunk 0) while scan runs ----
        // Stage 0's last reader was chunk 6, fenced by chunk 7's top sync.
        if (tc < 3) {
            const int m1 = m0 + MT;
            #pragma unroll
            for (int i = 0; i < 4; i++)
                rA[i] = *reinterpret_cast<const float4*>(
                    A + (size_t)(m1 + aRow[i]) * K_DIM + aC4 * 4);
            #pragma unroll
            for (int i = 0; i < 2; i++)
                cp_async16(sb + ASTG + (uint32_t)(bRow[i] * ROWB + bC16 * 16),
                           g_Wt + (size_t)(n0 + bRow[i]) * K_DIM + bC16 * 8);
            CP_COMMIT();
            #pragma unroll
            for (int i = 0; i < 4; i++)
                sts_round4(rA[i], sb + (uint32_t)(aRow[i] * ROWB + aC4 * 8));
        }

        // ---- dump acc (+bias) into scan buffer [t_local][n_local] ----
        // Scan buffer reuse across tiles is ordered by the next mainloop's
        // first __syncthreads (scan reads happen before any thread reaches it).
        #pragma unroll
        for (int nt = 0; nt < 8; nt++) {
            const int col = colBase + nt * 8;
            float2 bv = *reinterpret_cast<const float2*>(bias + n0 + col);
            #pragma unroll
            for (int mt = 0; mt < 2; mt++) {
                const int r = rowBase + mt * 16;
                float2 o0 = { acc[mt][nt][0] + bv.x, acc[mt][nt][1] + bv.y };
                float2 o1 = { acc[mt][nt][2] + bv.x, acc[mt][nt][3] + bv.y };
                *reinterpret_cast<float2*>(scf + (size_t)r * SCROW + col)       = o0;
                *reinterpret_cast<float2*>(scf + (size_t)(r + 8) * SCROW + col) = o1;
            }
        }
        __syncthreads();

        // ---- scan 128 steps; store results DIRECTLY to gmem (coalesced) ----
        if (tid < 128) {
            float* crow = C + (size_t)m0 * U_DIM + n0 + tid;
            #pragma unroll
            for (int t = 0; t < MT; t += 8) {
                float v[8];
                #pragma unroll
                for (int i = 0; i < 8; i++)
                    v[i] = scf[(size_t)(t + i) * SCROW + tid];
                #pragma unroll
                for (int i = 0; i < 8; i++) {
                    h = fmaxf(fmaf(h, uc, v[i]), 0.0f);
                    v[i] = h;
                }
                #pragma unroll
                for (int i = 0; i < 8; i++)
                    crow[(size_t)(t + i) * U_DIM] = v[i];
            }
        }
        // no trailing sync: next mainloop's chunk-0 sync provides ordering
    }
}

// ---------------------------------------------------------------- launch
extern "C" void kernel_launch(void* const* d_in, const int* in_sizes, int n_in,
                              void* d_out, int out_size)
{
    const float* x  = (const float*)d_in[0];  // [B,T,D]
    const float* h0 = (const float*)d_in[1];  // [B,U]
    const float* W  = (const float*)d_in[2];  // [D,U]
    const float* u  = (const float*)d_in[3];  // [U]
    const float* bb = (const float*)d_in[4];  // [U]
    float* out = (float*)d_out;               // [B,T,U]

    const int U = in_sizes[3];                // 512
    const int B = in_sizes[1] / U;            // 64
    const int D = in_sizes[2] / U;            // 256

    // 1) transpose + fp16-round W
    wsplit_kernel<<<dim3(U / 32, D / 32), dim3(32, 8)>>>(W);

    // 2) fused GEMM + scan
    cudaFuncSetAttribute(indrnn_fused_kernel,
                         cudaFuncAttributeMaxDynamicSharedMemorySize, SMEM_BYTES);
    dim3 gg(U / NT, B);   // (4, 64) = 256 CTAs, single wave at occ 2
    indrnn_fused_kernel<<<gg, 256, SMEM_BYTES>>>(x, bb, h0, u, out);
}